// round 5
// baseline (speedup 1.0000x reference)
#include <cuda_runtime.h>
#include <math.h>

#define NNODES 100000
#define NGRAPH 256
#define NCLASS 10
#define NEG 0.2f
#define MAXE 1300000
#define SBLK 1024
#define NSB ((NNODES + SBLK - 1) / SBLK)   // 98
#define FULLM 0xffffffffu

// ---------------- scratch (static device globals; no allocation) ----------------
__device__ __align__(16) float g_H[NNODES * 64];
__device__ __align__(16) float g_A[NNODES * 64];
__device__ __align__(16) float g_B[NNODES * 64];
__device__ float g_s[NNODES];
__device__ float g_d[NNODES];
__device__ int   g_cnt[NNODES];
__device__ int   g_rowstart[NNODES + 1];
__device__ int   g_rowcur[NNODES];
__device__ int   g_csrc[MAXE];
__device__ volatile int g_aggr[NSB];
__device__ volatile int g_incl[NSB];
__device__ volatile int g_flag[NSB];

__device__ __forceinline__ float lrelu(float x) { return x > 0.f ? x : NEG * x; }

// ---------------- CSR build ----------------

__global__ void k_zero() {
    int n = blockIdx.x * blockDim.x + threadIdx.x;
    if (n < NNODES) g_cnt[n] = 0;
    if (n < NSB) g_flag[n] = 0;
}

// 4 edges per thread (E assumed %4==0 when launched; host guarantees)
__global__ void k_hist4(const int* __restrict__ dst, int E4) {
    int i = blockIdx.x * blockDim.x + threadIdx.x;
    if (i >= E4) return;
    int4 d = reinterpret_cast<const int4*>(dst)[i];
    atomicAdd(&g_cnt[d.x], 1);
    atomicAdd(&g_cnt[d.y], 1);
    atomicAdd(&g_cnt[d.z], 1);
    atomicAdd(&g_cnt[d.w], 1);
}
__global__ void k_hist1(const int* __restrict__ dst, int E) {
    int e = blockIdx.x * blockDim.x + threadIdx.x;
    if (e < E) atomicAdd(&g_cnt[dst[e]], 1);
}

// single-kernel exclusive scan with decoupled lookback (98 blocks, all resident)
__global__ void k_scan() {
    __shared__ int sd[SBLK];
    __shared__ int s_prefix;
    int b = blockIdx.x;
    int i = b * SBLK + threadIdx.x;
    int v = (i < NNODES) ? g_cnt[i] : 0;
    sd[threadIdx.x] = v;
    __syncthreads();
    for (int off = 1; off < SBLK; off <<= 1) {
        int t = (threadIdx.x >= off) ? sd[threadIdx.x - off] : 0;
        __syncthreads();
        sd[threadIdx.x] += t;
        __syncthreads();
    }
    if (threadIdx.x == 0) {
        int agg = sd[SBLK - 1];
        if (b == 0) {
            g_incl[0] = agg;
            __threadfence();
            g_flag[0] = 2;
            s_prefix = 0;
        } else {
            g_aggr[b] = agg;
            __threadfence();
            g_flag[b] = 1;
            int sum = 0, j = b - 1;
            while (true) {
                int f;
                while ((f = g_flag[j]) == 0) {}
                if (f == 2) { sum += g_incl[j]; break; }
                sum += g_aggr[j];
                j--;
            }
            g_incl[b] = sum + agg;
            __threadfence();
            g_flag[b] = 2;
            s_prefix = sum;
        }
    }
    __syncthreads();
    int ex = s_prefix + sd[threadIdx.x] - v;
    if (i < NNODES) { g_rowstart[i] = ex; g_rowcur[i] = ex; }
    if (i == NNODES - 1) g_rowstart[NNODES] = ex + v;
}

__global__ void k_scatter4(const int* __restrict__ src, const int* __restrict__ dst, int E4) {
    int i = blockIdx.x * blockDim.x + threadIdx.x;
    if (i >= E4) return;
    int4 s = reinterpret_cast<const int4*>(src)[i];
    int4 d = reinterpret_cast<const int4*>(dst)[i];
    int p0 = atomicAdd(&g_rowcur[d.x], 1);
    int p1 = atomicAdd(&g_rowcur[d.y], 1);
    int p2 = atomicAdd(&g_rowcur[d.z], 1);
    int p3 = atomicAdd(&g_rowcur[d.w], 1);
    g_csrc[p0] = s.x;
    g_csrc[p1] = s.y;
    g_csrc[p2] = s.z;
    g_csrc[p3] = s.w;
}
__global__ void k_scatter1(const int* __restrict__ src, const int* __restrict__ dst, int E) {
    int e = blockIdx.x * blockDim.x + threadIdx.x;
    if (e >= E) return;
    int pos = atomicAdd(&g_rowcur[dst[e]], 1);
    g_csrc[pos] = src[e];
}

// ---------------- fused GEMM + attention coefficients ----------------
template <int FIN, int FOUT, int TPN>
__global__ void __launch_bounds__(256) k_gemmsd(const float* __restrict__ X,
                                                const float* __restrict__ W,
                                                const float* __restrict__ asrc,
                                                const float* __restrict__ adst,
                                                float* __restrict__ H) {
    constexpr int FO = FOUT / TPN;
    __shared__ float sw[FIN * FOUT];
    __shared__ float sa[FOUT], sdv[FOUT];
    for (int i = threadIdx.x; i < FIN * FOUT; i += 256) sw[i] = W[i];
    if (threadIdx.x < FOUT) {
        sa[threadIdx.x] = asrc[threadIdx.x];
        sdv[threadIdx.x] = adst[threadIdx.x];
    }
    __syncthreads();
    int t = blockIdx.x * 256 + threadIdx.x;
    int n = t / TPN, part = t % TPN;
    bool valid = n < NNODES;
    int nc = valid ? n : NNODES - 1;
    const float4* xr = reinterpret_cast<const float4*>(X + (long)nc * FIN);
    float acc[FO];
#pragma unroll
    for (int q = 0; q < FO; q++) acc[q] = 0.f;
#pragma unroll
    for (int k4 = 0; k4 < FIN / 4; k4++) {
        float4 xv = xr[k4];
        const float* wr = sw + (k4 * 4) * FOUT + part * FO;
#pragma unroll
        for (int q = 0; q < FO; q++) acc[q] = fmaf(xv.x, wr[q], acc[q]);
#pragma unroll
        for (int q = 0; q < FO; q++) acc[q] = fmaf(xv.y, wr[FOUT + q], acc[q]);
#pragma unroll
        for (int q = 0; q < FO; q++) acc[q] = fmaf(xv.z, wr[2 * FOUT + q], acc[q]);
#pragma unroll
        for (int q = 0; q < FO; q++) acc[q] = fmaf(xv.w, wr[3 * FOUT + q], acc[q]);
    }
    if (valid) {
        float* hr = H + (long)n * FOUT + part * FO;
#pragma unroll
        for (int q = 0; q < FO; q++) hr[q] = acc[q];
    }
    float s = 0.f, d = 0.f;
#pragma unroll
    for (int q = 0; q < FO; q++) {
        s = fmaf(acc[q], sa[part * FO + q], s);
        d = fmaf(acc[q], sdv[part * FO + q], d);
    }
    if (TPN == 2) {
        s += __shfl_xor_sync(FULLM, s, 1);
        d += __shfl_xor_sync(FULLM, d, 1);
    }
    if (valid && part == 0) { g_s[n] = s; g_d[n] = d; }
}

// ---------------- fused GAT aggregation: warp per dst node ----------------
// uses lrelu monotonicity: max_e lrelu(s_e + d_n) = lrelu(max_e s_e + d_n)
template <int FOUT>
__global__ void __launch_bounds__(256) k_layer(const float* __restrict__ H,
                                               const float* __restrict__ b,
                                               float* __restrict__ OUT) {
    constexpr int L4 = FOUT / 4;      // lanes per edge (float4 each)
    constexpr int EPI = 32 / L4;      // edges processed in parallel
    __shared__ int   ss[8][32];
    __shared__ float swm[8][32];
    int wid = threadIdx.x >> 5, lane = threadIdx.x & 31;
    int n = blockIdx.x * 8 + wid;
    if (n >= NNODES) return;

    float s_n = g_s[n];
    float d_n = g_d[n];
    int beg = g_rowstart[n], end = g_rowstart[n + 1];
    int deg = end - beg;

    int sub = lane / L4;
    int f0 = lane % L4;
    float4 acc = make_float4(0.f, 0.f, 0.f, 0.f);
    float den = 0.f;
    float m;

    if (deg <= 32) {
        // fast path: registers + shfl broadcast, no smem
        int s = 0;
        float sv = -3.4e38f;
        if (lane < deg) {
            s = g_csrc[beg + lane];
            sv = g_s[s];
        }
        float smax = fmaxf(sv, s_n);
#pragma unroll
        for (int o = 16; o > 0; o >>= 1)
            smax = fmaxf(smax, __shfl_xor_sync(FULLM, smax, o));
        m = lrelu(smax + d_n);
        float w = (lane < deg) ? __expf(lrelu(sv + d_n) - m) : 0.f;
        den = w;
        int trips = (deg + EPI - 1) / EPI;
        for (int i = 0; i < trips; i++) {
            int k = sub + i * EPI;
            int kk = k < deg ? k : 0;
            float wk = __shfl_sync(FULLM, w, kk);
            int sk = __shfl_sync(FULLM, s, kk);
            if (k < deg) {
                float4 h = reinterpret_cast<const float4*>(H + (long)sk * FOUT)[f0];
                acc.x = fmaf(wk, h.x, acc.x);
                acc.y = fmaf(wk, h.y, acc.y);
                acc.z = fmaf(wk, h.z, acc.z);
                acc.w = fmaf(wk, h.w, acc.w);
            }
        }
    } else {
        // rare path: chunked with smem staging
        float smax = s_n;
        for (int j = beg + lane; j < end; j += 32)
            smax = fmaxf(smax, g_s[g_csrc[j]]);
#pragma unroll
        for (int o = 16; o > 0; o >>= 1)
            smax = fmaxf(smax, __shfl_xor_sync(FULLM, smax, o));
        m = lrelu(smax + d_n);
        for (int cb = beg; cb < end; cb += 32) {
            int j = cb + lane;
            int s = 0;
            float w = 0.f;
            if (j < end) {
                s = g_csrc[j];
                w = __expf(lrelu(g_s[s] + d_n) - m);
            }
            den += w;
            ss[wid][lane] = s;
            swm[wid][lane] = w;
            __syncwarp();
            int cnt = min(32, end - cb);
#pragma unroll 2
            for (int k = sub; k < cnt; k += EPI) {
                float wk = swm[wid][k];
                long sk = ss[wid][k];
                float4 h = reinterpret_cast<const float4*>(H + sk * FOUT)[f0];
                acc.x = fmaf(wk, h.x, acc.x);
                acc.y = fmaf(wk, h.y, acc.y);
                acc.z = fmaf(wk, h.z, acc.z);
                acc.w = fmaf(wk, h.w, acc.w);
            }
            __syncwarp();
        }
    }

    // reduce den across lanes
#pragma unroll
    for (int o = 16; o > 0; o >>= 1) den += __shfl_xor_sync(FULLM, den, o);
    // combine edge-parallel sub-groups
#pragma unroll
    for (int o = L4; o < 32; o <<= 1) {
        acc.x += __shfl_xor_sync(FULLM, acc.x, o);
        acc.y += __shfl_xor_sync(FULLM, acc.y, o);
        acc.z += __shfl_xor_sync(FULLM, acc.z, o);
        acc.w += __shfl_xor_sync(FULLM, acc.w, o);
    }

    float wself = __expf(lrelu(s_n + d_n) - m);
    den += wself;
    float inv = 1.f / (den + 1e-16f);
    if (lane < L4) {
        float4 hn = reinterpret_cast<const float4*>(H + (long)n * FOUT)[f0];
        float4 bb = reinterpret_cast<const float4*>(b)[f0];
        float4 o4;
        o4.x = fmaxf(fmaf(wself, hn.x, acc.x) * inv + bb.x, 0.f);
        o4.y = fmaxf(fmaf(wself, hn.y, acc.y) * inv + bb.y, 0.f);
        o4.z = fmaxf(fmaf(wself, hn.z, acc.z) * inv + bb.z, 0.f);
        o4.w = fmaxf(fmaf(wself, hn.w, acc.w) * inv + bb.w, 0.f);
        reinterpret_cast<float4*>(OUT + (long)n * FOUT)[f0] = o4;
    }
}

// ---------------- fused pool + FC + log_softmax: one block per graph ----------------
__global__ void k_poolfc(const float* __restrict__ X, const int* __restrict__ batch,
                         const float* __restrict__ fcw, const float* __restrict__ fcb,
                         float* __restrict__ out) {
    int g = blockIdx.x;
    int t = threadIdx.x;
    __shared__ int lohi[2];
    if (t < 2) {
        int target = g + t;
        int lo = 0, hi = NNODES;
        while (lo < hi) {
            int mid = (lo + hi) >> 1;
            if (batch[mid] < target) lo = mid + 1; else hi = mid;
        }
        lohi[t] = lo;
    }
    __syncthreads();
    int f = t & 63, grp = t >> 6;
    float v = 0.f;   // inputs post-relu (>=0), segments non-empty
    for (int n = lohi[0] + grp; n < lohi[1]; n += 4)
        v = fmaxf(v, X[(long)n * 64 + f]);
    __shared__ float sm[256];
    __shared__ float p[64];
    sm[t] = v;
    __syncthreads();
    if (grp == 0)
        p[f] = fmaxf(fmaxf(sm[f], sm[f + 64]), fmaxf(sm[f + 128], sm[f + 192]));
    __syncthreads();
    __shared__ float lg[NCLASS];
    __shared__ float red[2];
    if (t < NCLASS) {
        float acc = fcb[t];
#pragma unroll
        for (int k = 0; k < 64; k++) acc = fmaf(p[k], fcw[k * NCLASS + t], acc);
        lg[t] = acc;
    }
    __syncthreads();
    if (t == 0) {
        float mx = lg[0];
#pragma unroll
        for (int i = 1; i < NCLASS; i++) mx = fmaxf(mx, lg[i]);
        float se = 0.f;
#pragma unroll
        for (int i = 0; i < NCLASS; i++) se += __expf(lg[i] - mx);
        red[0] = mx;
        red[1] = logf(se);
    }
    __syncthreads();
    if (t < NCLASS) out[g * NCLASS + t] = lg[t] - red[0] - red[1];
}

// ---------------- host ----------------

extern "C" void kernel_launch(void* const* d_in, const int* in_sizes, int n_in,
                              void* d_out, int out_size) {
    const float* x     = (const float*)d_in[0];
    const int*   ei    = (const int*)d_in[1];
    const int*   batch = (const int*)d_in[2];
    const float* W1 = (const float*)d_in[3];
    const float* a1s = (const float*)d_in[4];
    const float* a1d = (const float*)d_in[5];
    const float* b1 = (const float*)d_in[6];
    const float* W2 = (const float*)d_in[7];
    const float* a2s = (const float*)d_in[8];
    const float* a2d = (const float*)d_in[9];
    const float* b2 = (const float*)d_in[10];
    const float* W3 = (const float*)d_in[11];
    const float* a3s = (const float*)d_in[12];
    const float* a3d = (const float*)d_in[13];
    const float* b3 = (const float*)d_in[14];
    const float* fcw = (const float*)d_in[15];
    const float* fcb = (const float*)d_in[16];
    float* out = (float*)d_out;

    int E = in_sizes[1] / 2;
    const int* srcp = ei;
    const int* dstp = ei + E;

    float *H, *A, *B;
    cudaGetSymbolAddress((void**)&H, g_H);
    cudaGetSymbolAddress((void**)&A, g_A);
    cudaGetSymbolAddress((void**)&B, g_B);

    const int NT = 256;
    // CSR build (dst-sorted)
    k_zero<<<(NNODES + NT - 1) / NT, NT>>>();
    if ((E & 3) == 0) {
        int E4 = E >> 2;
        k_hist4<<<(E4 + NT - 1) / NT, NT>>>(dstp, E4);
    } else {
        k_hist1<<<(E + NT - 1) / NT, NT>>>(dstp, E);
    }
    k_scan<<<NSB, SBLK>>>();
    if ((E & 3) == 0) {
        int E4 = E >> 2;
        k_scatter4<<<(E4 + NT - 1) / NT, NT>>>(srcp, dstp, E4);
    } else {
        k_scatter1<<<(E + NT - 1) / NT, NT>>>(srcp, dstp, E);
    }

    // layer 1: 128 -> 16
    k_gemmsd<128, 16, 1><<<(NNODES + NT - 1) / NT, NT>>>(x, W1, a1s, a1d, H);
    k_layer<16><<<(NNODES + 7) / 8, NT>>>(H, b1, A);

    // layer 2: 16 -> 32
    k_gemmsd<16, 32, 1><<<(NNODES + NT - 1) / NT, NT>>>(A, W2, a2s, a2d, H);
    k_layer<32><<<(NNODES + 7) / 8, NT>>>(H, b2, B);

    // layer 3: 32 -> 64
    k_gemmsd<32, 64, 2><<<(NNODES * 2 + NT - 1) / NT, NT>>>(B, W3, a3s, a3d, H);
    k_layer<64><<<(NNODES + 7) / 8, NT>>>(H, b3, A);

    // pool + fc + log_softmax
    k_poolfc<<<NGRAPH, NT>>>(A, batch, fcw, fcb, out);
}

// round 6
// speedup vs baseline: 1.1780x; 1.1780x over previous
#include <cuda_runtime.h>
#include <math.h>

#define NNODES 100000
#define NGRAPH 256
#define NCLASS 10
#define NEG 0.2f
#define MAXE 1300000
#define SBLK 1024
#define NSB ((NNODES + SBLK - 1) / SBLK)   // 98
#define FULLM 0xffffffffu

// ---------------- scratch (static device globals; no allocation) ----------------
__device__ __align__(16) float g_H[NNODES * 64];
__device__ __align__(16) float g_A[NNODES * 64];
__device__ __align__(16) float g_B[NNODES * 64];
__device__ float g_s[NNODES];
__device__ float g_d[NNODES];
__device__ int   g_cnt[NNODES];       // zero at call entry (restored by k_scan)
__device__ int   g_rowstart[NNODES + 1];
__device__ int   g_rowcur[NNODES];
__device__ int   g_csrc[MAXE];
__device__ volatile int g_aggr[NSB];
__device__ volatile int g_incl[NSB];
__device__ volatile int g_flag[NSB];  // zero at call entry (restored by k_hist)

__device__ __forceinline__ float lrelu(float x) { return x > 0.f ? x : NEG * x; }

// ---------------- CSR build ----------------

// hist also re-zeros g_flag for this call's scan
__global__ void k_hist(const int* __restrict__ dst, int E) {
    int e = blockIdx.x * blockDim.x + threadIdx.x;
    if (e < NSB) g_flag[e] = 0;
    if (e < E) atomicAdd(&g_cnt[dst[e]], 1);
}

// single-kernel exclusive scan, decoupled lookback; consumes-and-zeroes g_cnt
__global__ void k_scan() {
    __shared__ int sd[SBLK];
    __shared__ int s_prefix;
    int b = blockIdx.x;
    int i = b * SBLK + threadIdx.x;
    int v = 0;
    if (i < NNODES) { v = g_cnt[i]; g_cnt[i] = 0; }   // restore zero for next call
    sd[threadIdx.x] = v;
    __syncthreads();
    for (int off = 1; off < SBLK; off <<= 1) {
        int t = (threadIdx.x >= off) ? sd[threadIdx.x - off] : 0;
        __syncthreads();
        sd[threadIdx.x] += t;
        __syncthreads();
    }
    if (threadIdx.x == 0) {
        int agg = sd[SBLK - 1];
        if (b == 0) {
            g_incl[0] = agg;
            __threadfence();
            g_flag[0] = 2;
            s_prefix = 0;
        } else {
            g_aggr[b] = agg;
            __threadfence();
            g_flag[b] = 1;
            int sum = 0, j = b - 1;
            while (true) {
                int f;
                while ((f = g_flag[j]) == 0) {}
                if (f == 2) { sum += g_incl[j]; break; }
                sum += g_aggr[j];
                j--;
            }
            g_incl[b] = sum + agg;
            __threadfence();
            g_flag[b] = 2;
            s_prefix = sum;
        }
    }
    __syncthreads();
    int ex = s_prefix + sd[threadIdx.x] - v;
    if (i < NNODES) { g_rowstart[i] = ex; g_rowcur[i] = ex; }
    if (i == NNODES - 1) g_rowstart[NNODES] = ex + v;
}

// ---------------- GEMM body (float4 smem weight reads) ----------------
template <int FIN, int FOUT, int TPN>
__device__ __forceinline__ void gemmsd_body(int bx, int tid,
                                            const float* __restrict__ X,
                                            const float* __restrict__ W,
                                            const float* __restrict__ asrc,
                                            const float* __restrict__ adst,
                                            float* __restrict__ H,
                                            float* smem) {
    constexpr int FO = FOUT / TPN;
    float* sw = smem;
    float* sa = smem + FIN * FOUT;
    float* sdv = sa + FOUT;
    for (int i = tid; i < FIN * FOUT; i += 256) sw[i] = W[i];
    if (tid < FOUT) { sa[tid] = asrc[tid]; sdv[tid] = adst[tid]; }
    __syncthreads();
    int t = bx * 256 + tid;
    int n = t / TPN, part = t % TPN;
    bool valid = n < NNODES;
    int nc = valid ? n : NNODES - 1;
    const float4* xr = reinterpret_cast<const float4*>(X + (long)nc * FIN);
    float acc[FO];
#pragma unroll
    for (int q = 0; q < FO; q++) acc[q] = 0.f;
#pragma unroll
    for (int k4 = 0; k4 < FIN / 4; k4++) {
        float4 xv = xr[k4];
        float xs[4] = {xv.x, xv.y, xv.z, xv.w};
#pragma unroll
        for (int r = 0; r < 4; r++) {
            const float4* wr = reinterpret_cast<const float4*>(
                sw + (k4 * 4 + r) * FOUT + part * FO);
#pragma unroll
            for (int q4 = 0; q4 < FO / 4; q4++) {
                float4 wv = wr[q4];
                acc[q4 * 4 + 0] = fmaf(xs[r], wv.x, acc[q4 * 4 + 0]);
                acc[q4 * 4 + 1] = fmaf(xs[r], wv.y, acc[q4 * 4 + 1]);
                acc[q4 * 4 + 2] = fmaf(xs[r], wv.z, acc[q4 * 4 + 2]);
                acc[q4 * 4 + 3] = fmaf(xs[r], wv.w, acc[q4 * 4 + 3]);
            }
        }
    }
    if (valid) {
        float4* hr = reinterpret_cast<float4*>(H + (long)n * FOUT + part * FO);
#pragma unroll
        for (int q4 = 0; q4 < FO / 4; q4++)
            hr[q4] = make_float4(acc[q4 * 4], acc[q4 * 4 + 1], acc[q4 * 4 + 2], acc[q4 * 4 + 3]);
    }
    float s = 0.f, d = 0.f;
#pragma unroll
    for (int q = 0; q < FO; q++) {
        s = fmaf(acc[q], sa[part * FO + q], s);
        d = fmaf(acc[q], sdv[part * FO + q], d);
    }
    if (TPN == 2) {
        s += __shfl_xor_sync(FULLM, s, 1);
        d += __shfl_xor_sync(FULLM, d, 1);
    }
    if (valid && part == 0) { g_s[n] = s; g_d[n] = d; }
}

template <int FIN, int FOUT, int TPN>
__global__ void __launch_bounds__(256) k_gemmsd(const float* __restrict__ X,
                                                const float* __restrict__ W,
                                                const float* __restrict__ asrc,
                                                const float* __restrict__ adst,
                                                float* __restrict__ H) {
    __shared__ float smem[FIN * FOUT + 2 * FOUT];
    gemmsd_body<FIN, FOUT, TPN>(blockIdx.x, threadIdx.x, X, W, asrc, adst, H, smem);
}

// fused: blocks [0, GB1) do gemm1; blocks [GB1, ...) do CSR scatter
#define GB1 ((NNODES + 255) / 256)
__global__ void __launch_bounds__(256) k_sg1(const int* __restrict__ src,
                                             const int* __restrict__ dst, int E,
                                             const float* __restrict__ X,
                                             const float* __restrict__ W,
                                             const float* __restrict__ asrc,
                                             const float* __restrict__ adst,
                                             float* __restrict__ H) {
    __shared__ float smem[128 * 16 + 32];
    if (blockIdx.x < GB1) {
        gemmsd_body<128, 16, 1>(blockIdx.x, threadIdx.x, X, W, asrc, adst, H, smem);
    } else {
        int e = (blockIdx.x - GB1) * 256 + threadIdx.x;
        if (e < E) {
            int pos = atomicAdd(&g_rowcur[dst[e]], 1);
            g_csrc[pos] = src[e];
        }
    }
}

// ---------------- fused GAT aggregation: warp per dst node ----------------
template <int FOUT>
__global__ void __launch_bounds__(256) k_layer(const float* __restrict__ H,
                                               const float* __restrict__ b,
                                               float* __restrict__ OUT) {
    constexpr int L4 = FOUT / 4;      // lanes per edge (float4 each)
    constexpr int EPI = 32 / L4;      // edges processed in parallel
    __shared__ int   ss[8][32];
    __shared__ float swm[8][32];
    int wid = threadIdx.x >> 5, lane = threadIdx.x & 31;
    int n = blockIdx.x * 8 + wid;
    if (n >= NNODES) return;

    float s_n = g_s[n];
    float d_n = g_d[n];
    int beg = g_rowstart[n], end = g_rowstart[n + 1];
    int deg = end - beg;

    int sub = lane / L4;
    int f0 = lane % L4;
    float4 acc = make_float4(0.f, 0.f, 0.f, 0.f);
    float den = 0.f;
    float m;

    if (deg <= 32) {
        // fast path: registers + shfl broadcast, no smem
        int s = 0;
        float sv = -3.4e38f;
        if (lane < deg) {
            s = g_csrc[beg + lane];
            sv = g_s[s];
        }
        float smax = fmaxf(sv, s_n);
#pragma unroll
        for (int o = 16; o > 0; o >>= 1)
            smax = fmaxf(smax, __shfl_xor_sync(FULLM, smax, o));
        m = lrelu(smax + d_n);
        float w = (lane < deg) ? __expf(lrelu(sv + d_n) - m) : 0.f;
        den = w;
        int trips = (deg + EPI - 1) / EPI;
#pragma unroll 4
        for (int i = 0; i < trips; i++) {
            int k = sub + i * EPI;
            int kk = k < deg ? k : 0;
            float wk = __shfl_sync(FULLM, w, kk);
            int sk = __shfl_sync(FULLM, s, kk);
            if (k < deg) {
                float4 h = reinterpret_cast<const float4*>(H + (long)sk * FOUT)[f0];
                acc.x = fmaf(wk, h.x, acc.x);
                acc.y = fmaf(wk, h.y, acc.y);
                acc.z = fmaf(wk, h.z, acc.z);
                acc.w = fmaf(wk, h.w, acc.w);
            }
        }
    } else {
        // rare path: chunked with smem staging
        float smax = s_n;
        for (int j = beg + lane; j < end; j += 32)
            smax = fmaxf(smax, g_s[g_csrc[j]]);
#pragma unroll
        for (int o = 16; o > 0; o >>= 1)
            smax = fmaxf(smax, __shfl_xor_sync(FULLM, smax, o));
        m = lrelu(smax + d_n);
        for (int cb = beg; cb < end; cb += 32) {
            int j = cb + lane;
            int s = 0;
            float w = 0.f;
            if (j < end) {
                s = g_csrc[j];
                w = __expf(lrelu(g_s[s] + d_n) - m);
            }
            den += w;
            ss[wid][lane] = s;
            swm[wid][lane] = w;
            __syncwarp();
            int cnt = min(32, end - cb);
#pragma unroll 2
            for (int k = sub; k < cnt; k += EPI) {
                float wk = swm[wid][k];
                long sk = ss[wid][k];
                float4 h = reinterpret_cast<const float4*>(H + sk * FOUT)[f0];
                acc.x = fmaf(wk, h.x, acc.x);
                acc.y = fmaf(wk, h.y, acc.y);
                acc.z = fmaf(wk, h.z, acc.z);
                acc.w = fmaf(wk, h.w, acc.w);
            }
            __syncwarp();
        }
    }

    // reduce den across lanes
#pragma unroll
    for (int o = 16; o > 0; o >>= 1) den += __shfl_xor_sync(FULLM, den, o);
    // combine edge-parallel sub-groups
#pragma unroll
    for (int o = L4; o < 32; o <<= 1) {
        acc.x += __shfl_xor_sync(FULLM, acc.x, o);
        acc.y += __shfl_xor_sync(FULLM, acc.y, o);
        acc.z += __shfl_xor_sync(FULLM, acc.z, o);
        acc.w += __shfl_xor_sync(FULLM, acc.w, o);
    }

    float wself = __expf(lrelu(s_n + d_n) - m);
    den += wself;
    float inv = 1.f / (den + 1e-16f);
    if (lane < L4) {
        float4 hn = reinterpret_cast<const float4*>(H + (long)n * FOUT)[f0];
        float4 bb = reinterpret_cast<const float4*>(b)[f0];
        float4 o4;
        o4.x = fmaxf(fmaf(wself, hn.x, acc.x) * inv + bb.x, 0.f);
        o4.y = fmaxf(fmaf(wself, hn.y, acc.y) * inv + bb.y, 0.f);
        o4.z = fmaxf(fmaf(wself, hn.z, acc.z) * inv + bb.z, 0.f);
        o4.w = fmaxf(fmaf(wself, hn.w, acc.w) * inv + bb.w, 0.f);
        reinterpret_cast<float4*>(OUT + (long)n * FOUT)[f0] = o4;
    }
}

// ---------------- fused pool + FC + log_softmax: one block per graph ----------------
__global__ void k_poolfc(const float* __restrict__ X, const int* __restrict__ batch,
                         const float* __restrict__ fcw, const float* __restrict__ fcb,
                         float* __restrict__ out) {
    int g = blockIdx.x;
    int t = threadIdx.x;
    __shared__ int lohi[2];
    if (t < 2) {
        int target = g + t;
        int lo = 0, hi = NNODES;
        while (lo < hi) {
            int mid = (lo + hi) >> 1;
            if (batch[mid] < target) lo = mid + 1; else hi = mid;
        }
        lohi[t] = lo;
    }
    __syncthreads();
    int f = t & 63, grp = t >> 6;
    float v = 0.f;   // inputs post-relu (>=0), segments non-empty
    for (int n = lohi[0] + grp; n < lohi[1]; n += 4)
        v = fmaxf(v, X[(long)n * 64 + f]);
    __shared__ float sm[256];
    __shared__ float p[64];
    sm[t] = v;
    __syncthreads();
    if (grp == 0)
        p[f] = fmaxf(fmaxf(sm[f], sm[f + 64]), fmaxf(sm[f + 128], sm[f + 192]));
    __syncthreads();
    __shared__ float lg[NCLASS];
    __shared__ float red[2];
    if (t < NCLASS) {
        float acc = fcb[t];
#pragma unroll
        for (int k = 0; k < 64; k++) acc = fmaf(p[k], fcw[k * NCLASS + t], acc);
        lg[t] = acc;
    }
    __syncthreads();
    if (t == 0) {
        float mx = lg[0];
#pragma unroll
        for (int i = 1; i < NCLASS; i++) mx = fmaxf(mx, lg[i]);
        float se = 0.f;
#pragma unroll
        for (int i = 0; i < NCLASS; i++) se += __expf(lg[i] - mx);
        red[0] = mx;
        red[1] = logf(se);
    }
    __syncthreads();
    if (t < NCLASS) out[g * NCLASS + t] = lg[t] - red[0] - red[1];
}

// ---------------- host ----------------

extern "C" void kernel_launch(void* const* d_in, const int* in_sizes, int n_in,
                              void* d_out, int out_size) {
    const float* x     = (const float*)d_in[0];
    const int*   ei    = (const int*)d_in[1];
    const int*   batch = (const int*)d_in[2];
    const float* W1 = (const float*)d_in[3];
    const float* a1s = (const float*)d_in[4];
    const float* a1d = (const float*)d_in[5];
    const float* b1 = (const float*)d_in[6];
    const float* W2 = (const float*)d_in[7];
    const float* a2s = (const float*)d_in[8];
    const float* a2d = (const float*)d_in[9];
    const float* b2 = (const float*)d_in[10];
    const float* W3 = (const float*)d_in[11];
    const float* a3s = (const float*)d_in[12];
    const float* a3d = (const float*)d_in[13];
    const float* b3 = (const float*)d_in[14];
    const float* fcw = (const float*)d_in[15];
    const float* fcb = (const float*)d_in[16];
    float* out = (float*)d_out;

    int E = in_sizes[1] / 2;
    const int* srcp = ei;
    const int* dstp = ei + E;

    float *H, *A, *B;
    cudaGetSymbolAddress((void**)&H, g_H);
    cudaGetSymbolAddress((void**)&A, g_A);
    cudaGetSymbolAddress((void**)&B, g_B);

    const int NT = 256;
    // 1: histogram (+ flag reset)
    k_hist<<<(E + NT - 1) / NT, NT>>>(dstp, E);
    // 2: scan (+ cnt reset)
    k_scan<<<NSB, SBLK>>>();
    // 3: fused CSR scatter + layer-1 GEMM
    k_sg1<<<GB1 + (E + NT - 1) / NT, NT>>>(srcp, dstp, E, x, W1, a1s, a1d, H);
    // 4: layer-1 aggregation (profiled slot)
    k_layer<16><<<(NNODES + 7) / 8, NT>>>(H, b1, A);

    // layer 2: 16 -> 32
    k_gemmsd<16, 32, 1><<<(NNODES + NT - 1) / NT, NT>>>(A, W2, a2s, a2d, H);
    k_layer<32><<<(NNODES + 7) / 8, NT>>>(H, b2, B);

    // layer 3: 32 -> 64
    k_gemmsd<32, 64, 2><<<(NNODES * 2 + NT - 1) / NT, NT>>>(B, W3, a3s, a3d, H);
    k_layer<64><<<(NNODES + 7) / 8, NT>>>(H, b3, A);

    // pool + fc + log_softmax
    k_poolfc<<<NGRAPH, NT>>>(A, batch, fcw, fcb, out);
}